// round 1
// baseline (speedup 1.0000x reference)
#include <cuda_runtime.h>

#define BSZ 256
#define MAX_LEN 1024
#define D 256
#define D_ATTN 128

// scratch: g[b][j] = sum_a tanh(trans_q + b_f) * w_h
__device__ float g_buf[BSZ * D];

// ---------------------------------------------------------------------------
// Kernel 1: per block (b_half, j): GEMM 128(b) x 128(a) x 256(k),
// fused tanh + weighted reduction over a -> g[b][j].
// grid (2, 256), block 256 threads (16 tx over a, 16 ty over b), 8x8 micro-tile
// with split 4+4 fragments for conflict-free LDS.128.
// ---------------------------------------------------------------------------
__global__ void __launch_bounds__(256, 2) k1_gemm_tanh(
    const float* __restrict__ emb_q,   // [BSZ, D]
    const float* __restrict__ w_f,     // [D, D_ATTN, D]
    const float* __restrict__ b_f,     // [D, D_ATTN]
    const float* __restrict__ w_h)     // [D_ATTN]
{
    const int j   = blockIdx.y;
    const int b0  = blockIdx.x * 128;
    const int tid = threadIdx.x;
    const int tx  = tid & 15;   // a dimension
    const int ty  = tid >> 4;   // b dimension

    // transposed tiles: [k][row], pad 132 so float4 reads are 16B-aligned
    __shared__ float As[32][132];   // emb_q tile  [k][b]
    __shared__ float Bs[32][132];   // w_f tile    [k][a]
    __shared__ float red[16][128];  // cross-tx reduction

    float acc[8][8];
#pragma unroll
    for (int i = 0; i < 8; i++)
#pragma unroll
        for (int c = 0; c < 8; c++) acc[i][c] = 0.0f;

    const float* Amat = emb_q + (size_t)b0 * D;              // [128][256]
    const float* Bmat = w_f + (size_t)j * D_ATTN * D;        // [128][256]

    const int lane = tid & 31;
    const int warp = tid >> 5;

    for (int kk = 0; kk < D; kk += 32) {
        // load 128x32 tiles, transposed into smem (coalesced 128B global reads)
#pragma unroll
        for (int r = 0; r < 16; r++) {
            const int row = warp * 16 + r;
            As[lane][row] = Amat[row * D + kk + lane];
            Bs[lane][row] = Bmat[row * D + kk + lane];
        }
        __syncthreads();

#pragma unroll
        for (int k = 0; k < 32; k++) {
            const float4 a0 = *(const float4*)&As[k][ty * 4];
            const float4 a1 = *(const float4*)&As[k][64 + ty * 4];
            const float4 bv0 = *(const float4*)&Bs[k][tx * 4];
            const float4 bv1 = *(const float4*)&Bs[k][64 + tx * 4];
            const float af[8] = {a0.x, a0.y, a0.z, a0.w, a1.x, a1.y, a1.z, a1.w};
            const float bf[8] = {bv0.x, bv0.y, bv0.z, bv0.w, bv1.x, bv1.y, bv1.z, bv1.w};
#pragma unroll
            for (int i = 0; i < 8; i++)
#pragma unroll
                for (int c = 0; c < 8; c++)
                    acc[i][c] = fmaf(af[i], bf[c], acc[i][c]);
        }
        __syncthreads();
    }

    // epilogue: tanh(acc + bias) * w_h, reduce over the a dimension
    float bias[8], wh[8];
#pragma unroll
    for (int c = 0; c < 8; c++) {
        const int a = tx * 4 + (c & 3) + (c >> 2) * 64;
        bias[c] = b_f[j * D_ATTN + a];
        wh[c]   = w_h[a];
    }
    float part[8];
#pragma unroll
    for (int i = 0; i < 8; i++) part[i] = 0.0f;
#pragma unroll
    for (int i = 0; i < 8; i++)
#pragma unroll
        for (int c = 0; c < 8; c++)
            part[i] += tanhf(acc[i][c] + bias[c]) * wh[c];

#pragma unroll
    for (int i = 0; i < 8; i++) {
        const int bi = ty * 4 + (i & 3) + (i >> 2) * 64;
        red[tx][bi] = part[i];
    }
    __syncthreads();

    if (tid < 128) {
        float s = 0.0f;
#pragma unroll
        for (int t = 0; t < 16; t++) s += red[t][tid];
        g_buf[(size_t)(b0 + tid) * D + j] = s;
    }
}

// ---------------------------------------------------------------------------
// Kernel 2: out[b,l] = sum_j emb_iseq[b,l,j] * g[b,j]
// warp-per-row, float4 loads (fully coalesced), butterfly reduce.
// grid (MAX_LEN/8, BSZ), block 256 (8 warps = 8 rows)
// ---------------------------------------------------------------------------
__global__ void __launch_bounds__(256) k2_weight(
    const float* __restrict__ emb_iseq,  // [BSZ, MAX_LEN, D]
    float* __restrict__ out)             // [BSZ, MAX_LEN]
{
    const int b  = blockIdx.y;
    const int l0 = blockIdx.x * 8;
    const int tid = threadIdx.x;

    __shared__ float gs[D];
    gs[tid] = g_buf[(size_t)b * D + tid];
    __syncthreads();

    const int warp = tid >> 5;
    const int lane = tid & 31;
    const int l = l0 + warp;

    const float4* row = (const float4*)(emb_iseq + ((size_t)b * MAX_LEN + l) * D);
    const float4* gv  = (const float4*)gs;

    float acc = 0.0f;
#pragma unroll
    for (int i = 0; i < 2; i++) {
        const float4 e = row[lane + i * 32];
        const float4 g = gv[lane + i * 32];
        acc += e.x * g.x + e.y * g.y + e.z * g.z + e.w * g.w;
    }
#pragma unroll
    for (int o = 16; o; o >>= 1) acc += __shfl_xor_sync(0xffffffffu, acc, o);

    if (lane == 0) out[(size_t)b * MAX_LEN + l] = acc;
}

// ---------------------------------------------------------------------------

extern "C" void kernel_launch(void* const* d_in, const int* in_sizes, int n_in,
                              void* d_out, int out_size)
{
    const float* emb_q    = (const float*)d_in[0];
    const float* emb_iseq = (const float*)d_in[1];
    const float* w_f      = (const float*)d_in[2];
    const float* b_f      = (const float*)d_in[3];
    const float* w_h      = (const float*)d_in[4];
    float* out = (float*)d_out;

    dim3 g1(2, D);  // (b_half, j)
    k1_gemm_tanh<<<g1, 256>>>(emb_q, w_f, b_f, w_h);

    dim3 g2(MAX_LEN / 8, BSZ);
    k2_weight<<<g2, 256>>>(emb_iseq, out);
}

// round 2
// speedup vs baseline: 2.1230x; 2.1230x over previous
#include <cuda_runtime.h>
#include <cstdint>

#define BSZ 256
#define MAX_LEN 1024
#define D 256
#define D_ATTN 128

// scratch: g[b][j] = sum_a tanh(trans_q + b_f) * w_h
__device__ float g_buf[BSZ * D];

#define PAD 44   // floats per smem row; (12*r + c) % 32 is a permutation for
                 // r in 0..7, c in 0..3  -> conflict-free mma fragment loads,
                 // and 44*4 bytes is 16B-aligned -> STS.128 legal.

__device__ __forceinline__ uint32_t f2tf32(float x) {
    uint32_t r;
    asm("cvt.rna.tf32.f32 %0, %1;" : "=r"(r) : "f"(x));
    return r;
}

__device__ __forceinline__ float tanh_ap(float x) {
    float r;
    asm("tanh.approx.f32 %0, %1;" : "=f"(r) : "f"(x));
    return r;
}

__device__ __forceinline__ void mma_tf32(float c[4], const uint32_t a[4], const uint32_t b[2]) {
    asm volatile(
        "mma.sync.aligned.m16n8k8.row.col.f32.tf32.tf32.f32 "
        "{%0,%1,%2,%3}, {%4,%5,%6,%7}, {%8,%9}, {%0,%1,%2,%3};\n"
        : "+f"(c[0]), "+f"(c[1]), "+f"(c[2]), "+f"(c[3])
        : "r"(a[0]), "r"(a[1]), "r"(a[2]), "r"(a[3]), "r"(b[0]), "r"(b[1]));
}

// ---------------------------------------------------------------------------
// Kernel 1: per block (b_half, j): tf32 tensor-core GEMM 128(a) x 128(b) x 256(k)
// fused tanh + weighted reduction over a -> g[b][j].
// grid (2, 256), block 256 = 8 warps arranged 4(m over a) x 2(n over b).
// Warp tile 32(a) x 64(b): 2 m-frags x 8 n-frags of m16n8k8.
// ---------------------------------------------------------------------------
__global__ void __launch_bounds__(256, 2) k1_mma_tanh(
    const float* __restrict__ emb_q,   // [BSZ, D]
    const float* __restrict__ w_f,     // [D, D_ATTN, D]
    const float* __restrict__ b_f,     // [D, D_ATTN]
    const float* __restrict__ w_h)     // [D_ATTN]
{
    const int j    = blockIdx.y;
    const int b0   = blockIdx.x * 128;
    const int tid  = threadIdx.x;
    const int lane = tid & 31;
    const int warp = tid >> 5;
    const int wm   = warp & 3;     // a-tile of warp (0..3)
    const int wn   = warp >> 2;    // b-tile of warp (0..1)
    const int gid  = lane >> 2;    // 0..7
    const int tid4 = lane & 3;     // 0..3

    __shared__ uint32_t As[128 * PAD];  // [a][k] tf32 bits
    __shared__ uint32_t Bs[128 * PAD];  // [b][k] tf32 bits
    __shared__ float red[4][128];

    float acc[2][8][4];
#pragma unroll
    for (int mf = 0; mf < 2; mf++)
#pragma unroll
        for (int nf = 0; nf < 8; nf++)
#pragma unroll
            for (int c = 0; c < 4; c++) acc[mf][nf][c] = 0.0f;

    const float* Ag = w_f  + (size_t)j  * D_ATTN * D;  // [128][256]
    const float* Bg = emb_q + (size_t)b0 * D;          // [128][256]

    for (int kt = 0; kt < 8; kt++) {
        const int kk = kt * 32;
        // Tile load: quad index q in [0,1024): row=q>>3, kq=q&7.
        // Consecutive lanes -> consecutive quads -> warp covers 4 full 128B rows.
#pragma unroll
        for (int i = 0; i < 4; i++) {
            const int q   = tid + i * 256;
            const int row = q >> 3;
            const int kq  = q & 7;
            float4 va = *(const float4*)&Ag[(size_t)row * D + kk + kq * 4];
            float4 vb = *(const float4*)&Bg[(size_t)row * D + kk + kq * 4];
            uint4 ua = make_uint4(f2tf32(va.x), f2tf32(va.y), f2tf32(va.z), f2tf32(va.w));
            uint4 ub = make_uint4(f2tf32(vb.x), f2tf32(vb.y), f2tf32(vb.z), f2tf32(vb.w));
            *(uint4*)&As[row * PAD + kq * 4] = ua;
            *(uint4*)&Bs[row * PAD + kq * 4] = ub;
        }
        __syncthreads();

#pragma unroll
        for (int ks = 0; ks < 4; ks++) {
            const int kb = ks * 8;
            uint32_t a[2][4], b[8][2];
#pragma unroll
            for (int mf = 0; mf < 2; mf++) {
                const int r0 = wm * 32 + mf * 16 + gid;
                a[mf][0] = As[(r0    ) * PAD + kb + tid4    ];
                a[mf][1] = As[(r0 + 8) * PAD + kb + tid4    ];
                a[mf][2] = As[(r0    ) * PAD + kb + tid4 + 4];
                a[mf][3] = As[(r0 + 8) * PAD + kb + tid4 + 4];
            }
#pragma unroll
            for (int nf = 0; nf < 8; nf++) {
                const int rn = wn * 64 + nf * 8 + gid;
                b[nf][0] = Bs[rn * PAD + kb + tid4    ];
                b[nf][1] = Bs[rn * PAD + kb + tid4 + 4];
            }
#pragma unroll
            for (int mf = 0; mf < 2; mf++)
#pragma unroll
                for (int nf = 0; nf < 8; nf++)
                    mma_tf32(acc[mf][nf], a[mf], b[nf]);
        }
        __syncthreads();
    }

    // Epilogue: tanh(acc + bias[a]) * w_h[a], reduce over a.
    float bias[2][2], wh[2][2];
#pragma unroll
    for (int mf = 0; mf < 2; mf++)
#pragma unroll
        for (int h = 0; h < 2; h++) {
            const int a_idx = wm * 32 + mf * 16 + h * 8 + gid;
            bias[mf][h] = b_f[j * D_ATTN + a_idx];
            wh[mf][h]   = w_h[a_idx];
        }

#pragma unroll
    for (int nf = 0; nf < 8; nf++) {
        float p0 = 0.0f, p1 = 0.0f;
#pragma unroll
        for (int mf = 0; mf < 2; mf++) {
            p0 += tanh_ap(acc[mf][nf][0] + bias[mf][0]) * wh[mf][0]
                + tanh_ap(acc[mf][nf][2] + bias[mf][1]) * wh[mf][1];
            p1 += tanh_ap(acc[mf][nf][1] + bias[mf][0]) * wh[mf][0]
                + tanh_ap(acc[mf][nf][3] + bias[mf][1]) * wh[mf][1];
        }
#pragma unroll
        for (int o = 4; o <= 16; o <<= 1) {
            p0 += __shfl_xor_sync(0xffffffffu, p0, o);
            p1 += __shfl_xor_sync(0xffffffffu, p1, o);
        }
        if (gid == 0) {
            const int col = wn * 64 + nf * 8 + tid4 * 2;
            red[wm][col]     = p0;
            red[wm][col + 1] = p1;
        }
    }
    __syncthreads();

    if (tid < 128) {
        float s = red[0][tid] + red[1][tid] + red[2][tid] + red[3][tid];
        g_buf[(size_t)(b0 + tid) * D + j] = s;
    }
}

// ---------------------------------------------------------------------------
// Kernel 2: out[b,l] = sum_j emb_iseq[b,l,j] * g[b,j]
// 4 rows per warp, all 8 LDG.128 issued front-batched (MLP=8), streaming hint.
// grid (MAX_LEN/32, BSZ), block 256.
// ---------------------------------------------------------------------------
__global__ void __launch_bounds__(256) k2_weight(
    const float* __restrict__ emb_iseq,  // [BSZ, MAX_LEN, D]
    float* __restrict__ out)             // [BSZ, MAX_LEN]
{
    const int b   = blockIdx.y;
    const int l0  = blockIdx.x * 32;
    const int tid = threadIdx.x;

    __shared__ float gs[D];
    gs[tid] = g_buf[(size_t)b * D + tid];
    __syncthreads();

    const int warp = tid >> 5;
    const int lane = tid & 31;
    const int l = l0 + warp * 4;

    const float4* base = (const float4*)(emb_iseq + ((size_t)b * MAX_LEN + l) * D);

    float4 e[4][2];
#pragma unroll
    for (int r = 0; r < 4; r++)
#pragma unroll
        for (int i = 0; i < 2; i++)
            e[r][i] = __ldcs(&base[r * 64 + i * 32 + lane]);

    const float4* gv = (const float4*)gs;
    const float4 g0 = gv[lane];
    const float4 g1 = gv[lane + 32];

    float acc[4];
#pragma unroll
    for (int r = 0; r < 4; r++) {
        acc[r] = e[r][0].x * g0.x + e[r][0].y * g0.y + e[r][0].z * g0.z + e[r][0].w * g0.w
               + e[r][1].x * g1.x + e[r][1].y * g1.y + e[r][1].z * g1.z + e[r][1].w * g1.w;
    }
#pragma unroll
    for (int r = 0; r < 4; r++)
#pragma unroll
        for (int o = 16; o; o >>= 1)
            acc[r] += __shfl_xor_sync(0xffffffffu, acc[r], o);

    if (lane == 0) {
#pragma unroll
        for (int r = 0; r < 4; r++)
            out[(size_t)b * MAX_LEN + l + r] = acc[r];
    }
}

// ---------------------------------------------------------------------------

extern "C" void kernel_launch(void* const* d_in, const int* in_sizes, int n_in,
                              void* d_out, int out_size)
{
    const float* emb_q    = (const float*)d_in[0];
    const float* emb_iseq = (const float*)d_in[1];
    const float* w_f      = (const float*)d_in[2];
    const float* b_f      = (const float*)d_in[3];
    const float* w_h      = (const float*)d_in[4];
    float* out = (float*)d_out;

    dim3 g1(2, D);  // (b_half, j)
    k1_mma_tanh<<<g1, 256>>>(emb_q, w_f, b_f, w_h);

    dim3 g2(MAX_LEN / 32, BSZ);
    k2_weight<<<g2, 256>>>(emb_iseq, out);
}

// round 4
// speedup vs baseline: 2.1337x; 1.0051x over previous
#include <cuda_runtime.h>
#include <cstdint>

#define BSZ 256
#define MAX_LEN 1024
#define D 256
#define D_ATTN 128

// scratch
__device__ float g_buf[BSZ * D];            // g[b][j]
__device__ uint32_t emb_tf32[BSZ * D];      // pre-rounded emb_q (tf32 bits)

// ---------------------------------------------------------------------------
__device__ __forceinline__ uint32_t smem_u32(const void* p) {
    uint32_t a;
    asm("{ .reg .u64 t; cvta.to.shared.u64 t, %1; cvt.u32.u64 %0, t; }"
        : "=r"(a) : "l"(p));
    return a;
}
__device__ __forceinline__ uint32_t f2tf32(float x) {
    uint32_t r;
    asm("cvt.rna.tf32.f32 %0, %1;" : "=r"(r) : "f"(x));
    return r;
}
__device__ __forceinline__ float tanh_ap(float x) {
    float r;
    asm("tanh.approx.f32 %0, %1;" : "=f"(r) : "f"(x));
    return r;
}
__device__ __forceinline__ uint32_t swz(uint32_t x) {
    return x ^ ((x >> 3) & 0x70);
}
__device__ __forceinline__ void mma_tf32(float c[4], const uint32_t a[4],
                                         const uint32_t b[2]) {
    asm volatile(
        "mma.sync.aligned.m16n8k8.row.col.f32.tf32.tf32.f32 "
        "{%0,%1,%2,%3}, {%4,%5,%6,%7}, {%8,%9}, {%0,%1,%2,%3};\n"
        : "+f"(c[0]), "+f"(c[1]), "+f"(c[2]), "+f"(c[3])
        : "r"(a[0]), "r"(a[1]), "r"(a[2]), "r"(a[3]), "r"(b[0]), "r"(b[1]));
}
#define LDSM4(r0, r1, r2, r3, addr)                                           \
    asm volatile("ldmatrix.sync.aligned.m8n8.x4.shared.b16 {%0,%1,%2,%3}, [%4];" \
                 : "=r"(r0), "=r"(r1), "=r"(r2), "=r"(r3) : "r"(addr))
#define CP16(dst, src)                                                        \
    asm volatile("cp.async.cg.shared.global [%0], [%1], 16;" ::"r"(dst),      \
                 "l"(src) : "memory")
#define CP_COMMIT() asm volatile("cp.async.commit_group;" ::: "memory")
#define CP_WAIT(n) asm volatile("cp.async.wait_group %0;" ::"n"(n) : "memory")

// ---------------------------------------------------------------------------
// Kernel 0: pre-round emb_q to tf32 bits (runs once per launch, tiny)
// ---------------------------------------------------------------------------
__global__ void k0_cvt(const float* __restrict__ emb_q) {
    const int i = blockIdx.x * blockDim.x + threadIdx.x;  // 16384 float4
    const float4 v = ((const float4*)emb_q)[i];
    ((uint4*)emb_tf32)[i] =
        make_uint4(f2tf32(v.x), f2tf32(v.y), f2tf32(v.z), f2tf32(v.w));
}

// ---------------------------------------------------------------------------
// Kernel 1: one CTA per j. D[m=a(128), n=b(256)] = w_f[j] . emb_q^T, K=256.
// A (w_f) converted inline exactly once; B (emb_q) streamed pre-converted via
// cp.async. ldmatrix fragment loads, 3-stage pipeline, fused tanh+w_h epilogue.
// 8 warps: wm = wid>>2 (2 m-tiles of 64), wn = wid&3 (4 n-tiles of 64).
// Warp tile m64 x n64: mf=4 m16-blocks, nf=8 n8-blocks.
// ---------------------------------------------------------------------------
#define STG 49152           // per stage: A 16KB @0, B 32KB @16384
#define B_OFF 16384
#define K1_DSMEM (3 * STG + 1024)

__global__ void __launch_bounds__(256, 1) k1_mma(
    const float* __restrict__ w_f,     // [D, D_ATTN, D]
    const float* __restrict__ b_f,     // [D, D_ATTN]
    const float* __restrict__ w_h)     // [D_ATTN]
{
    extern __shared__ char dyn[];
    __shared__ float bias_s[D_ATTN], wh_s[D_ATTN];
    __shared__ float red[2][256];

    const int j    = blockIdx.x;
    const int tid  = threadIdx.x;
    const int lane = tid & 31;
    const int wid  = tid >> 5;
    const int wm   = wid >> 2;     // 0..1  (m = a dim)
    const int wn   = wid & 3;      // 0..3  (n = b dim)
    const int gid  = lane >> 2;
    const int tid4 = lane & 3;

    const uint32_t raw = smem_u32(dyn);
    const uint32_t dbase = (raw + 1023u) & ~1023u;
    char* dptr = dyn + (dbase - raw);

    if (tid < D_ATTN) {
        bias_s[tid] = b_f[j * D_ATTN + tid];
        wh_s[tid]   = w_h[tid];
    }

    // ---- per-thread tile-load coords (A rows 0..127 use i<4; B rows 0..255 i<8)
    const int kq = tid & 7;
    const int rb = tid >> 3;
    uint32_t sts[8];
    int gidx[8];
#pragma unroll
    for (int i = 0; i < 8; i++) {
        const int r = rb + 32 * i;
        sts[i]  = swz((uint32_t)r * 128 + kq * 16);
        gidx[i] = r * D + kq * 4;
    }

    // ---- ldmatrix per-thread address bases
    const int lrow = lane & 7, msel = lane >> 3;
    uint32_t rbA[4], rbB[4];
    {
        const int halfA = msel & 1, chA = msel >> 1;
        const int blkB = msel >> 1, chB = msel & 1;
#pragma unroll
        for (int m = 0; m < 4; m++) {
            const int rowA = (wm * 4 + m) * 16 + halfA * 8 + lrow;
            rbA[m] = (uint32_t)rowA * 128 + chA * 16;
        }
#pragma unroll
        for (int p = 0; p < 4; p++) {
            const int rowB = (wn * 8 + 2 * p + blkB) * 8 + lrow;
            rbB[p] = (uint32_t)rowB * 128 + chB * 16;
        }
    }

    const float* Aj = w_f + (size_t)j * D_ATTN * D;

    float acc[4][8][4];
#pragma unroll
    for (int m = 0; m < 4; m++)
#pragma unroll
        for (int n = 0; n < 8; n++)
#pragma unroll
            for (int c = 0; c < 4; c++) acc[m][n][c] = 0.0f;

    // ---- prologue: B(0)->s0, B(1)->s1 via cp.async; A(0) -> s0 via regs
    float4 ra[4];
#pragma unroll
    for (int i = 0; i < 8; i++)
        CP16(dbase + B_OFF + sts[i], (const char*)emb_tf32 + (size_t)(gidx[i]) * 4);
    CP_COMMIT();
#pragma unroll
    for (int i = 0; i < 8; i++)
        CP16(dbase + STG + B_OFF + sts[i],
             (const char*)emb_tf32 + (size_t)(gidx[i] + 32) * 4);
    CP_COMMIT();
#pragma unroll
    for (int i = 0; i < 4; i++) ra[i] = *(const float4*)(Aj + gidx[i]);
#pragma unroll
    for (int i = 0; i < 4; i++)
        *(uint4*)(dptr + sts[i]) = make_uint4(f2tf32(ra[i].x), f2tf32(ra[i].y),
                                              f2tf32(ra[i].z), f2tf32(ra[i].w));
    CP_WAIT(1);
    __syncthreads();

    // ---- main loop over 8 k-tiles of 32
#pragma unroll 1
    for (int t = 0; t < 8; t++) {
        const int s = t % 3;
        const uint32_t sb = dbase + (uint32_t)s * STG;

        if (t < 7) {
#pragma unroll
            for (int i = 0; i < 4; i++)
                ra[i] = *(const float4*)(Aj + gidx[i] + (t + 1) * 32);
        }
        if (t < 6) {
            const uint32_t db = dbase + (uint32_t)((t + 2) % 3) * STG + B_OFF;
#pragma unroll
            for (int i = 0; i < 8; i++)
                CP16(db + sts[i],
                     (const char*)emb_tf32 + (size_t)(gidx[i] + (t + 2) * 32) * 4);
            CP_COMMIT();
        }

        // compute this k-tile
#pragma unroll
        for (int ks = 0; ks < 4; ks++) {
            const uint32_t kb = (uint32_t)ks * 32;
            uint32_t af[4][4], bf[8][2];
#pragma unroll
            for (int m = 0; m < 4; m++)
                LDSM4(af[m][0], af[m][1], af[m][2], af[m][3],
                      sb + swz(rbA[m] + kb));
#pragma unroll
            for (int p = 0; p < 4; p++) {
                uint32_t r0, r1, r2, r3;
                LDSM4(r0, r1, r2, r3, sb + B_OFF + swz(rbB[p] + kb));
                bf[2 * p][0] = r0; bf[2 * p][1] = r1;
                bf[2 * p + 1][0] = r2; bf[2 * p + 1][1] = r3;
            }
#pragma unroll
            for (int m = 0; m < 4; m++)
#pragma unroll
                for (int n = 0; n < 8; n++) mma_tf32(acc[m][n], af[m], bf[n]);
        }
        __syncthreads();

        if (t < 7) {
            char* dp = dptr + (size_t)((t + 1) % 3) * STG;
#pragma unroll
            for (int i = 0; i < 4; i++)
                *(uint4*)(dp + sts[i]) =
                    make_uint4(f2tf32(ra[i].x), f2tf32(ra[i].y),
                               f2tf32(ra[i].z), f2tf32(ra[i].w));
        }
        if (t < 6) { CP_WAIT(1); }
        else if (t == 6) { CP_WAIT(0); }
        __syncthreads();
    }

    // ---- epilogue: g[b][j] = sum_a tanh(D[a,b] + bias[a]) * wh[a]
    float biasv[4][2], whv[4][2];
#pragma unroll
    for (int m = 0; m < 4; m++)
#pragma unroll
        for (int h = 0; h < 2; h++) {
            const int a = wm * 64 + m * 16 + h * 8 + gid;
            biasv[m][h] = bias_s[a];
            whv[m][h]   = wh_s[a];
        }

#pragma unroll
    for (int n = 0; n < 8; n++) {
        float p0 = 0.0f, p1 = 0.0f;
#pragma unroll
        for (int m = 0; m < 4; m++) {
            p0 += tanh_ap(acc[m][n][0] + biasv[m][0]) * whv[m][0]
                + tanh_ap(acc[m][n][2] + biasv[m][1]) * whv[m][1];
            p1 += tanh_ap(acc[m][n][1] + biasv[m][0]) * whv[m][0]
                + tanh_ap(acc[m][n][3] + biasv[m][1]) * whv[m][1];
        }
#pragma unroll
        for (int o = 4; o <= 16; o <<= 1) {
            p0 += __shfl_xor_sync(0xffffffffu, p0, o);
            p1 += __shfl_xor_sync(0xffffffffu, p1, o);
        }
        if (gid == 0) {
            const int col = wn * 64 + n * 8 + tid4 * 2;
            red[wm][col]     = p0;
            red[wm][col + 1] = p1;
        }
    }
    __syncthreads();
    g_buf[(size_t)tid * D + j] = red[0][tid] + red[1][tid];
}

// ---------------------------------------------------------------------------
// Kernel 2: out[b,l] = sum_j emb_iseq[b,l,j] * g[b,j]
// 8 rows per warp: 16 front-batched LDG.128 per lane, streaming.
// grid (MAX_LEN/64, BSZ), block 256.
// ---------------------------------------------------------------------------
__global__ void __launch_bounds__(256) k2_weight(
    const float* __restrict__ emb_iseq,  // [BSZ, MAX_LEN, D]
    float* __restrict__ out)             // [BSZ, MAX_LEN]
{
    const int b   = blockIdx.y;
    const int l0  = blockIdx.x * 64;
    const int tid = threadIdx.x;

    __shared__ float gs[D];
    gs[tid] = g_buf[(size_t)b * D + tid];
    __syncthreads();

    const int warp = tid >> 5;
    const int lane = tid & 31;
    const int l = l0 + warp * 8;

    const float4* base = (const float4*)(emb_iseq + ((size_t)b * MAX_LEN + l) * D);

    float4 e[8][2];
#pragma unroll
    for (int r = 0; r < 8; r++)
#pragma unroll
        for (int i = 0; i < 2; i++)
            e[r][i] = __ldcs(&base[r * 64 + i * 32 + lane]);

    const float4* gv = (const float4*)gs;
    const float4 g0 = gv[lane];
    const float4 g1 = gv[lane + 32];

    float acc[8];
#pragma unroll
    for (int r = 0; r < 8; r++) {
        acc[r] = e[r][0].x * g0.x + e[r][0].y * g0.y + e[r][0].z * g0.z + e[r][0].w * g0.w
               + e[r][1].x * g1.x + e[r][1].y * g1.y + e[r][1].z * g1.z + e[r][1].w * g1.w;
    }
#pragma unroll
    for (int r = 0; r < 8; r++)
#pragma unroll
        for (int o = 16; o; o >>= 1)
            acc[r] += __shfl_xor_sync(0xffffffffu, acc[r], o);

    if (lane == 0) {
#pragma unroll
        for (int r = 0; r < 8; r++)
            out[(size_t)b * MAX_LEN + l + r] = acc[r];
    }
}

// ---------------------------------------------------------------------------

extern "C" void kernel_launch(void* const* d_in, const int* in_sizes, int n_in,
                              void* d_out, int out_size)
{
    const float* emb_q    = (const float*)d_in[0];
    const float* emb_iseq = (const float*)d_in[1];
    const float* w_f      = (const float*)d_in[2];
    const float* b_f      = (const float*)d_in[3];
    const float* w_h      = (const float*)d_in[4];
    float* out = (float*)d_out;

    cudaFuncSetAttribute(k1_mma, cudaFuncAttributeMaxDynamicSharedMemorySize,
                         K1_DSMEM);

    k0_cvt<<<64, 256>>>(emb_q);
    k1_mma<<<D, 256, K1_DSMEM>>>(w_f, b_f, w_h);

    dim3 g2(MAX_LEN / 64, BSZ);
    k2_weight<<<g2, 256>>>(emb_iseq, out);
}

// round 5
// speedup vs baseline: 2.5308x; 1.1861x over previous
#include <cuda_runtime.h>
#include <cuda_fp16.h>
#include <cstdint>

#define BSZ 256
#define MAX_LEN 1024
#define D 256
#define D_ATTN 128

// scratch
__device__ float g_buf[BSZ * D];       // g[b][j]
__device__ __half emb_h[BSZ * D];      // pre-converted emb_q (fp16)

// ---------------------------------------------------------------------------
__device__ __forceinline__ uint32_t smem_u32(const void* p) {
    uint32_t a;
    asm("{ .reg .u64 t; cvta.to.shared.u64 t, %1; cvt.u32.u64 %0, t; }"
        : "=r"(a) : "l"(p));
    return a;
}
__device__ __forceinline__ float tanh_ap(float x) {
    float r;
    asm("tanh.approx.f32 %0, %1;" : "=f"(r) : "f"(x));
    return r;
}
__device__ __forceinline__ void mma_f16(float c[4], const uint32_t a[4],
                                        const uint32_t b[2]) {
    asm volatile(
        "mma.sync.aligned.m16n8k16.row.col.f32.f16.f16.f32 "
        "{%0,%1,%2,%3}, {%4,%5,%6,%7}, {%8,%9}, {%0,%1,%2,%3};\n"
        : "+f"(c[0]), "+f"(c[1]), "+f"(c[2]), "+f"(c[3])
        : "r"(a[0]), "r"(a[1]), "r"(a[2]), "r"(a[3]), "r"(b[0]), "r"(b[1]));
}
#define LDSM4(r0, r1, r2, r3, addr)                                           \
    asm volatile("ldmatrix.sync.aligned.m8n8.x4.shared.b16 {%0,%1,%2,%3}, [%4];" \
                 : "=r"(r0), "=r"(r1), "=r"(r2), "=r"(r3) : "r"(addr))
#define CP16(dst, src)                                                        \
    asm volatile("cp.async.cg.shared.global [%0], [%1], 16;" ::"r"(dst),      \
                 "l"(src) : "memory")
#define CP_COMMIT() asm volatile("cp.async.commit_group;" ::: "memory")
#define CP_WAIT(n) asm volatile("cp.async.wait_group %0;" ::"n"(n) : "memory")

__device__ __forceinline__ uint32_t pack_h2(float x, float y) {
    const __half2 h = __floats2half2_rn(x, y);
    return *(const uint32_t*)&h;
}

// ---------------------------------------------------------------------------
// Kernel 0: emb_q fp32 -> fp16
// ---------------------------------------------------------------------------
__global__ void k0_cvt(const float* __restrict__ emb_q) {
    const int i = blockIdx.x * blockDim.x + threadIdx.x;  // 16384 float4
    const float4 v = ((const float4*)emb_q)[i];
    ((uint2*)emb_h)[i] = make_uint2(pack_h2(v.x, v.y), pack_h2(v.z, v.w));
}

// ---------------------------------------------------------------------------
// Kernel 1: one CTA per j. D[m=a(128), n=b(256)] = w_f[j] . emb_q^T, K=256,
// fp16 mma m16n8k16, fp32 accum. B (emb_q fp16, 128KB) fully CTA-resident via
// 4 cp.async groups; A (w_f) converted inline, 2-stage 16KB double buffer.
// 8 warps: wm = wid>>2 (m 64-range), wn = wid&3 (n 64-range).
// smem rows = 128B (64 fp16), swizzle chunk c' = c ^ (r&7).
// ---------------------------------------------------------------------------
#define A_STG 16384
#define B_BASE 32768
#define B_TILE 32768
#define K1_DSMEM (B_BASE + 4 * B_TILE + 1024)   // 161KB + align

__global__ void __launch_bounds__(256, 1) k1_mma(
    const float* __restrict__ w_f,     // [D, D_ATTN, D]
    const float* __restrict__ b_f,     // [D, D_ATTN]
    const float* __restrict__ w_h)     // [D_ATTN]
{
    extern __shared__ char dyn[];
    __shared__ float bias_s[D_ATTN], wh_s[D_ATTN];
    __shared__ float red[2][256];

    const int j    = blockIdx.x;
    const int tid  = threadIdx.x;
    const int lane = tid & 31;
    const int wid  = tid >> 5;
    const int wm   = wid >> 2;
    const int wn   = wid & 3;
    const int gid  = lane >> 2;
    const int tid4 = lane & 3;

    const uint32_t raw = smem_u32(dyn);
    const uint32_t dbase = (raw + 1023u) & ~1023u;

    if (tid < D_ATTN) {
        bias_s[tid] = b_f[j * D_ATTN + tid];
        wh_s[tid]   = w_h[tid];
    }

    const int c  = tid & 7;       // 16B chunk within row
    const int rb = tid >> 3;      // row base (0..31)

    // ---- B: issue all 4 k-tiles as cp.async groups (once per CTA)
#pragma unroll
    for (int kt = 0; kt < 4; kt++) {
#pragma unroll
        for (int i = 0; i < 8; i++) {
            const int r = rb + 32 * i;  // 0..255
            const uint32_t dst = dbase + B_BASE + kt * B_TILE +
                                 r * 128 + ((c ^ (r & 7)) << 4);
            const char* src = (const char*)emb_h +
                              ((size_t)r * 256 + kt * 64 + c * 8) * 2;
            CP16(dst, src);
        }
        CP_COMMIT();
    }

    // ---- A tile 0: load + convert + STS
    const float* Aj = w_f + (size_t)j * D_ATTN * D;
    float4 ra[4][2];
#pragma unroll
    for (int i = 0; i < 4; i++) {
        const int r = rb + 32 * i;  // 0..127
        const float* p = Aj + (size_t)r * 256 + c * 8;
        ra[i][0] = *(const float4*)p;
        ra[i][1] = *(const float4*)(p + 4);
    }
#pragma unroll
    for (int i = 0; i < 4; i++) {
        const int r = rb + 32 * i;
        *(uint4*)(dyn + (dbase - raw) + r * 128 + ((c ^ (r & 7)) << 4)) =
            make_uint4(pack_h2(ra[i][0].x, ra[i][0].y),
                       pack_h2(ra[i][0].z, ra[i][0].w),
                       pack_h2(ra[i][1].x, ra[i][1].y),
                       pack_h2(ra[i][1].z, ra[i][1].w));
    }
    CP_WAIT(3);
    __syncthreads();

    // ---- ldmatrix per-thread bases
    const int lrow = lane & 7;
    const int half = (lane >> 3) & 1;
    const int hi   = lane >> 4;
    uint32_t roffA[4], swzA[4], roffB[4], swzB[4];
#pragma unroll
    for (int m = 0; m < 4; m++) {
        const int r = wm * 64 + m * 16 + half * 8 + lrow;
        roffA[m] = (uint32_t)r * 128;
        swzA[m]  = (uint32_t)(r & 7);
    }
#pragma unroll
    for (int p = 0; p < 4; p++) {
        const int r = wn * 64 + p * 16 + half * 8 + lrow;
        roffB[p] = (uint32_t)r * 128;
        swzB[p]  = (uint32_t)(r & 7);
    }

    float acc[4][8][4];
#pragma unroll
    for (int m = 0; m < 4; m++)
#pragma unroll
        for (int n = 0; n < 8; n++)
#pragma unroll
            for (int q = 0; q < 4; q++) acc[m][n][q] = 0.0f;

    // ---- main loop: 4 k-tiles (hand-unrolled for constant wait_group)
#pragma unroll
    for (int t = 0; t < 4; t++) {
        // prefetch next A tile
        if (t < 3) {
#pragma unroll
            for (int i = 0; i < 4; i++) {
                const int r = rb + 32 * i;
                const float* p = Aj + (size_t)r * 256 + (t + 1) * 64 + c * 8;
                ra[i][0] = *(const float4*)p;
                ra[i][1] = *(const float4*)(p + 4);
            }
        }

        // compute tile t
        const uint32_t aB = dbase + (uint32_t)(t & 1) * A_STG;
        const uint32_t bB = dbase + B_BASE + (uint32_t)t * B_TILE;
#pragma unroll
        for (int ks = 0; ks < 4; ks++) {
            const uint32_t ch = (uint32_t)(ks * 2 + hi);
            uint32_t af[4][4], bf[8][2];
#pragma unroll
            for (int m = 0; m < 4; m++)
                LDSM4(af[m][0], af[m][1], af[m][2], af[m][3],
                      aB + roffA[m] + ((ch ^ swzA[m]) << 4));
#pragma unroll
            for (int p = 0; p < 4; p++) {
                uint32_t r0, r1, r2, r3;
                LDSM4(r0, r1, r2, r3, bB + roffB[p] + ((ch ^ swzB[p]) << 4));
                bf[2 * p][0] = r0; bf[2 * p + 1][0] = r1;
                bf[2 * p][1] = r2; bf[2 * p + 1][1] = r3;
            }
#pragma unroll
            for (int m = 0; m < 4; m++)
#pragma unroll
                for (int n = 0; n < 8; n++) mma_f16(acc[m][n], af[m], bf[n]);
        }

        if (t < 3) {
            __syncthreads();
            char* dp = dyn + (dbase - raw) + ((t + 1) & 1) * A_STG;
#pragma unroll
            for (int i = 0; i < 4; i++) {
                const int r = rb + 32 * i;
                *(uint4*)(dp + r * 128 + ((c ^ (r & 7)) << 4)) =
                    make_uint4(pack_h2(ra[i][0].x, ra[i][0].y),
                               pack_h2(ra[i][0].z, ra[i][0].w),
                               pack_h2(ra[i][1].x, ra[i][1].y),
                               pack_h2(ra[i][1].z, ra[i][1].w));
            }
            if (t == 0) CP_WAIT(2);
            else if (t == 1) CP_WAIT(1);
            else CP_WAIT(0);
            __syncthreads();
        }
    }

    // ---- epilogue: g[b][j] = sum_a tanh(D[a,b] + bias[a]) * wh[a]
    float biasv[4][2], whv[4][2];
#pragma unroll
    for (int m = 0; m < 4; m++)
#pragma unroll
        for (int h = 0; h < 2; h++) {
            const int a = wm * 64 + m * 16 + h * 8 + gid;
            biasv[m][h] = bias_s[a];
            whv[m][h]   = wh_s[a];
        }

#pragma unroll
    for (int n = 0; n < 8; n++) {
        float p0 = 0.0f, p1 = 0.0f;
#pragma unroll
        for (int m = 0; m < 4; m++) {
            p0 += tanh_ap(acc[m][n][0] + biasv[m][0]) * whv[m][0]
                + tanh_ap(acc[m][n][2] + biasv[m][1]) * whv[m][1];
            p1 += tanh_ap(acc[m][n][1] + biasv[m][0]) * whv[m][0]
                + tanh_ap(acc[m][n][3] + biasv[m][1]) * whv[m][1];
        }
#pragma unroll
        for (int o = 4; o <= 16; o <<= 1) {
            p0 += __shfl_xor_sync(0xffffffffu, p0, o);
            p1 += __shfl_xor_sync(0xffffffffu, p1, o);
        }
        if (gid == 0) {
            const int col = wn * 64 + n * 8 + tid4 * 2;
            red[wm][col]     = p0;
            red[wm][col + 1] = p1;
        }
    }
    __syncthreads();
    g_buf[(size_t)tid * D + j] = red[0][tid] + red[1][tid];
}

// ---------------------------------------------------------------------------
// Kernel 2: out[b,l] = sum_j emb_iseq[b,l,j] * g[b,j]   (unchanged)
// ---------------------------------------------------------------------------
__global__ void __launch_bounds__(256) k2_weight(
    const float* __restrict__ emb_iseq,  // [BSZ, MAX_LEN, D]
    float* __restrict__ out)             // [BSZ, MAX_LEN]
{
    const int b   = blockIdx.y;
    const int l0  = blockIdx.x * 64;
    const int tid = threadIdx.x;

    __shared__ float gs[D];
    gs[tid] = g_buf[(size_t)b * D + tid];
    __syncthreads();

    const int warp = tid >> 5;
    const int lane = tid & 31;
    const int l = l0 + warp * 8;

    const float4* base = (const float4*)(emb_iseq + ((size_t)b * MAX_LEN + l) * D);

    float4 e[8][2];
#pragma unroll
    for (int r = 0; r < 8; r++)
#pragma unroll
        for (int i = 0; i < 2; i++)
            e[r][i] = __ldcs(&base[r * 64 + i * 32 + lane]);

    const float4* gv = (const float4*)gs;
    const float4 g0 = gv[lane];
    const float4 g1 = gv[lane + 32];

    float acc[8];
#pragma unroll
    for (int r = 0; r < 8; r++) {
        acc[r] = e[r][0].x * g0.x + e[r][0].y * g0.y + e[r][0].z * g0.z + e[r][0].w * g0.w
               + e[r][1].x * g1.x + e[r][1].y * g1.y + e[r][1].z * g1.z + e[r][1].w * g1.w;
    }
#pragma unroll
    for (int r = 0; r < 8; r++)
#pragma unroll
        for (int o = 16; o; o >>= 1)
            acc[r] += __shfl_xor_sync(0xffffffffu, acc[r], o);

    if (lane == 0) {
#pragma unroll
        for (int r = 0; r < 8; r++)
            out[(size_t)b * MAX_LEN + l + r] = acc[r];
    }
}

// ---------------------------------------------------------------------------

extern "C" void kernel_launch(void* const* d_in, const int* in_sizes, int n_in,
                              void* d_out, int out_size)
{
    const float* emb_q    = (const float*)d_in[0];
    const float* emb_iseq = (const float*)d_in[1];
    const float* w_f      = (const float*)d_in[2];
    const float* b_f      = (const float*)d_in[3];
    const float* w_h      = (const float*)d_in[4];
    float* out = (float*)d_out;

    cudaFuncSetAttribute(k1_mma, cudaFuncAttributeMaxDynamicSharedMemorySize,
                         K1_DSMEM);

    k0_cvt<<<64, 256>>>(emb_q);
    k1_mma<<<D, 256, K1_DSMEM>>>(w_f, b_f, w_h);

    dim3 g2(MAX_LEN / 64, BSZ);
    k2_weight<<<g2, 256>>>(emb_iseq, out);
}